// round 15
// baseline (speedup 1.0000x reference)
#include <cuda_runtime.h>
#include <cuda_fp16.h>
#include <math.h>
#include <stdint.h>

#define N_TOK 4096
#define DMODEL 1024
#define MLP 4096
#define NEXP 8

// ---------------- device scratch ----------------
__device__ float  g_p[N_TOK];
__device__ int    g_route[N_TOK];
__device__ int    g_cnt[NEXP];
__device__ int    g_off[NEXP + 1];
__device__ int    g_fill[NEXP];
__device__ int    g_perm[N_TOK];
__device__ int    g_done;
__device__ __half g_Xh[(size_t)N_TOK * DMODEL];          // gathered inputs, fp16
__device__ __half g_Hh[(size_t)N_TOK * MLP];             // hidden activations, fp16
__device__ __half g_W1h[(size_t)NEXP * DMODEL * MLP];    // 64 MB fp16 weights
__device__ __half g_W2h[(size_t)NEXP * MLP * DMODEL];    // 64 MB fp16 weights

// ---------------- weight conversion (fp32 -> fp16) ----------------
#define W_F4 8388608   // float4 count per weight tensor (8*1024*4096/4)
__global__ void convert_kernel(const float* __restrict__ W1, const float* __restrict__ W2) {
    int gid = blockIdx.x * 256 + threadIdx.x;          // 16384 blocks * 256
    const int NT = 16384 * 256;
#pragma unroll
    for (int q = 0; q < 4; q++) {
        int idx = gid + q * NT;
        const float4* src; __half* dst;
        if (idx < W_F4) { src = reinterpret_cast<const float4*>(W1) + idx; dst = g_W1h + (size_t)idx * 4; }
        else            { src = reinterpret_cast<const float4*>(W2) + (idx - W_F4); dst = g_W2h + (size_t)(idx - W_F4) * 4; }
        float4 v = *src;
        __half2 h0 = __floats2half2_rn(v.x, v.y);
        __half2 h1 = __floats2half2_rn(v.z, v.w);
        uint2 o;
        o.x = *reinterpret_cast<uint32_t*>(&h0);
        o.y = *reinterpret_cast<uint32_t*>(&h1);
        *reinterpret_cast<uint2*>(dst) = o;
    }
}

// ---------------- router (+ fused scan in last block) ----------------
__global__ void router_kernel(const float* __restrict__ x,
                              const float* __restrict__ wg,
                              const float* __restrict__ bg) {
    __shared__ float sw[DMODEL * NEXP];
    int tid = threadIdx.x;
    for (int i = tid; i < DMODEL * NEXP; i += 128) sw[i] = wg[i];
    __syncthreads();
    int t = blockIdx.x * 128 + tid;
    const float* xr = x + (size_t)t * DMODEL;
    float acc[NEXP];
#pragma unroll
    for (int e = 0; e < NEXP; e++) acc[e] = bg[e];
    for (int d = 0; d < DMODEL; d++) {
        float xv = xr[d];
#pragma unroll
        for (int e = 0; e < NEXP; e++) acc[e] += xv * sw[d * NEXP + e];
    }
    float mx = acc[0]; int mi = 0;
#pragma unroll
    for (int e = 1; e < NEXP; e++) if (acc[e] > mx) { mx = acc[e]; mi = e; }
    float s = 0.f;
#pragma unroll
    for (int e = 0; e < NEXP; e++) s += expf(acc[e] - mx);
    g_p[t] = 1.0f / s;
    g_route[t] = mi;
    atomicAdd(&g_cnt[mi], 1);

    __threadfence();
    __syncthreads();
    if (tid == 0) {
        int v = atomicAdd(&g_done, 1);
        if (v == (int)gridDim.x - 1) {
            __threadfence();
            int acc2 = 0;
            for (int e = 0; e < NEXP; e++) {
                int c = g_cnt[e];
                g_off[e] = acc2; g_fill[e] = acc2; acc2 += c;
                g_cnt[e] = 0;                 // reset for next launch
            }
            g_off[NEXP] = acc2;
            g_done = 0;                       // reset for next launch
            __threadfence();
        }
    }
}

// ---------------- scatter + gather fused ----------------
// 32 blocks x 128 threads; each thread owns one token: get dest row, then the
// block cooperatively copies its 128 rows (fp32 -> fp16).
__global__ void scatter_gather_kernel(const float* __restrict__ x) {
    __shared__ int s_pos[128];
    int tid = threadIdx.x;
    int t = blockIdx.x * 128 + tid;
    int e = g_route[t];
    int pos = atomicAdd(&g_fill[e], 1);
    s_pos[tid] = pos;
    g_perm[pos] = t;
    __syncthreads();
    for (int r = 0; r < 128; r++) {
        int tok = blockIdx.x * 128 + r;
        int pp = s_pos[r];
        const float4* src = reinterpret_cast<const float4*>(x + (size_t)tok * DMODEL);
#pragma unroll
        for (int j = 0; j < 2; j++) {
            int idx = tid + j * 128;          // 0..255 float4
            float4 v = src[idx];
            __half2 h0 = __floats2half2_rn(v.x, v.y);
            __half2 h1 = __floats2half2_rn(v.z, v.w);
            uint2 o;
            o.x = *reinterpret_cast<uint32_t*>(&h0);
            o.y = *reinterpret_cast<uint32_t*>(&h1);
            *reinterpret_cast<uint2*>(g_Xh + (size_t)pp * DMODEL + idx * 4) = o;
        }
    }
}

// ---------------- fp16 tensor-core grouped GEMM, cp.async 3-stage ----------------
#define BM 128
#define BN 128
#define BK 64
#define NST 3
#define AST_B 144                    // A row stride bytes (72 halves)
#define BST_B 272                    // B row stride bytes (136 halves)
#define ASTG (BM * AST_B)            // 18432 B / stage
#define BSTG (BK * BST_B)            // 17408 B / stage
#define STG (ASTG + BSTG)            // 35840
#define SMEM_TOT (NST * STG)         // 107520

__device__ __forceinline__ void cp16(uint32_t dst, const void* src, uint32_t sz) {
    asm volatile("cp.async.cg.shared.global [%0], [%1], 16, %2;"
                 :: "r"(dst), "l"(src), "r"(sz));
}
__device__ __forceinline__ void cp_commit() { asm volatile("cp.async.commit_group;"); }
__device__ __forceinline__ void cp_wait1()  { asm volatile("cp.async.wait_group 1;"); }

__device__ __forceinline__ void ldsm_x4(uint32_t& r0, uint32_t& r1, uint32_t& r2, uint32_t& r3,
                                        uint32_t addr) {
    asm volatile("ldmatrix.sync.aligned.m8n8.x4.shared.b16 {%0,%1,%2,%3}, [%4];"
                 : "=r"(r0), "=r"(r1), "=r"(r2), "=r"(r3) : "r"(addr));
}
__device__ __forceinline__ void ldsm_x4_t(uint32_t& r0, uint32_t& r1, uint32_t& r2, uint32_t& r3,
                                          uint32_t addr) {
    asm volatile("ldmatrix.sync.aligned.m8n8.x4.trans.shared.b16 {%0,%1,%2,%3}, [%4];"
                 : "=r"(r0), "=r"(r1), "=r"(r2), "=r"(r3) : "r"(addr));
}
__device__ __forceinline__ void mma_fp16(float c[4], const uint32_t a[4], const uint32_t b[2]) {
    asm volatile(
        "mma.sync.aligned.m16n8k16.row.col.f32.f16.f16.f32 "
        "{%0,%1,%2,%3}, {%4,%5,%6,%7}, {%8,%9}, {%0,%1,%2,%3};\n"
        : "+f"(c[0]), "+f"(c[1]), "+f"(c[2]), "+f"(c[3])
        : "r"(a[0]), "r"(a[1]), "r"(a[2]), "r"(a[3]), "r"(b[0]), "r"(b[1]));
}

// issue one stage's cp.async fills (A 1024 chunks, B 1024 chunks of 16B)
__device__ __forceinline__ void issue_stage(uint32_t sA, uint32_t sB,
                                            const __half* A, const __half* Bg,
                                            int K, int N, int k0, int mrows, int tid) {
#pragma unroll
    for (int i = 0; i < 4; i++) {
        int c = tid + 256 * i;
        int row = c >> 3;                         // 0..127
        int col8 = (c & 7) * 8;                   // halves
        const __half* src = A + (size_t)(row < mrows ? row : 0) * K + k0 + col8;
        cp16(sA + row * AST_B + (c & 7) * 16, src, row < mrows ? 16u : 0u);
    }
#pragma unroll
    for (int i = 0; i < 4; i++) {
        int c = tid + 256 * i;
        int row = c >> 4;                         // 0..63
        int col16 = (c & 15);                     // 16B chunk
        const __half* src = Bg + (size_t)(k0 + row) * N + col16 * 8;
        cp16(sB + row * BST_B + col16 * 16, src, 16u);
    }
    cp_commit();
}

// EPI = 1: Cdst = g_Hh (half), relu(A@B + bias)
// EPI = 2: Cdst = out (float), (A@B + bias) * p[tok], row-scattered
template <int EPI>
__global__ __launch_bounds__(256)
void gemm_fp16(const __half* __restrict__ Bmat, const float* __restrict__ bias_all,
               const __half* __restrict__ Asrc, void* __restrict__ Cdst,
               int K, int N) {
    int e = blockIdx.z;
    int row_end = g_off[e + 1];
    int row0 = g_off[e] + blockIdx.y * BM;
    if (row0 >= row_end) return;
    int mrows = min(row_end - row0, BM);
    int n0 = blockIdx.x * BN;

    const __half* A = Asrc + (size_t)row0 * K;
    const __half* Bg = Bmat + (size_t)e * K * N + n0;

    extern __shared__ char smem[];
    uint32_t s32 = (uint32_t)__cvta_generic_to_shared(smem);

    int tid = threadIdx.x;
    int warp = tid >> 5, lane = tid & 31;
    int wm = (warp >> 2) * 64;
    int wn = (warp & 3) * 32;
    int g = lane >> 2, tig = lane & 3;

    float c[4][4][4];
#pragma unroll
    for (int i = 0; i < 4; i++)
#pragma unroll
        for (int j = 0; j < 4; j++)
#pragma unroll
            for (int r = 0; r < 4; r++) c[i][j][r] = 0.f;

    uint32_t a_lane = (uint32_t)((wm + (lane & 15)) * AST_B + (lane >> 4) * 16);
    uint32_t b_lane = (uint32_t)(((lane & 7) + ((lane >> 3) & 1) * 8) * BST_B
                                 + (wn + (lane >> 4) * 8) * 2);

    const int nch = K / BK;

    // prologue: fill stages 0,1
#pragma unroll
    for (int s = 0; s < NST - 1; s++)
        issue_stage(s32 + s * STG, s32 + s * STG + ASTG, A, Bg, K, N, s * BK, mrows, tid);

    for (int ch = 0; ch < nch; ch++) {
        cp_wait1();
        __syncthreads();

        // refill stage ch+2 (its old contents were consumed in iteration ch-1)
        if (ch + NST - 1 < nch) {
            int s = (ch + NST - 1) % NST;
            issue_stage(s32 + s * STG, s32 + s * STG + ASTG, A, Bg, K, N,
                        (ch + NST - 1) * BK, mrows, tid);
        } else {
            cp_commit();   // keep group count in lockstep for wait_group 1
        }

        // compute on stage ch%NST
        uint32_t abase = s32 + (ch % NST) * STG + a_lane;
        uint32_t bbase = s32 + (ch % NST) * STG + ASTG + b_lane;
#pragma unroll
        for (int ks = 0; ks < 4; ks++) {
            int kk = ks * 16;
            uint32_t af[4][4], bf[4][2];
#pragma unroll
            for (int i = 0; i < 4; i++)
                ldsm_x4(af[i][0], af[i][1], af[i][2], af[i][3],
                        abase + (uint32_t)(i * 16 * AST_B + kk * 2));
#pragma unroll
            for (int jp = 0; jp < 2; jp++)
                ldsm_x4_t(bf[2 * jp][0], bf[2 * jp][1], bf[2 * jp + 1][0], bf[2 * jp + 1][1],
                          bbase + (uint32_t)(kk * BST_B + jp * 32));
#pragma unroll
            for (int i = 0; i < 4; i++)
#pragma unroll
                for (int j = 0; j < 4; j++) mma_fp16(c[i][j], af[i], bf[j]);
        }
        __syncthreads();
    }

    // ---------------- epilogue ----------------
    const float* bias = bias_all + (size_t)e * N + n0;
#pragma unroll
    for (int i = 0; i < 4; i++) {
#pragma unroll
        for (int r2 = 0; r2 < 2; r2++) {
            int mr = wm + i * 16 + g + r2 * 8;
            if (mr >= mrows) continue;
            int grow = row0 + mr;
            if (EPI == 1) {
                __half* orow = (__half*)Cdst + (size_t)grow * N + n0;
#pragma unroll
                for (int j = 0; j < 4; j++) {
                    int nc = wn + j * 8 + 2 * tig;
                    float v0 = c[i][j][2 * r2]     + bias[nc];
                    float v1 = c[i][j][2 * r2 + 1] + bias[nc + 1];
                    v0 = v0 > 0.f ? v0 : 0.f;
                    v1 = v1 > 0.f ? v1 : 0.f;
                    __half2 h = __floats2half2_rn(v0, v1);
                    *reinterpret_cast<__half2*>(orow + nc) = h;
                }
            } else {
                int tok = g_perm[grow];
                float p = g_p[tok];
                float* orow = (float*)Cdst + (size_t)tok * N + n0;
#pragma unroll
                for (int j = 0; j < 4; j++) {
                    int nc = wn + j * 8 + 2 * tig;
                    float2 o;
                    o.x = (c[i][j][2 * r2]     + bias[nc])     * p;
                    o.y = (c[i][j][2 * r2 + 1] + bias[nc + 1]) * p;
                    *reinterpret_cast<float2*>(orow + nc) = o;
                }
            }
        }
    }
}

// ---------------- launch ----------------
extern "C" void kernel_launch(void* const* d_in, const int* in_sizes, int n_in,
                              void* d_out, int out_size) {
    const float* x   = (const float*)d_in[0];
    const float* wg  = (const float*)d_in[1];
    const float* bg  = (const float*)d_in[2];
    const float* W1  = (const float*)d_in[3];
    const float* b1  = (const float*)d_in[4];
    const float* W2  = (const float*)d_in[5];
    const float* b2  = (const float*)d_in[6];
    float* out = (float*)d_out;

    cudaFuncSetAttribute(gemm_fp16<1>, cudaFuncAttributeMaxDynamicSharedMemorySize, SMEM_TOT);
    cudaFuncSetAttribute(gemm_fp16<2>, cudaFuncAttributeMaxDynamicSharedMemorySize, SMEM_TOT);

    __half *dX = nullptr, *dH = nullptr, *dW1h = nullptr, *dW2h = nullptr;
    cudaGetSymbolAddress((void**)&dX, g_Xh);
    cudaGetSymbolAddress((void**)&dH, g_Hh);
    cudaGetSymbolAddress((void**)&dW1h, g_W1h);
    cudaGetSymbolAddress((void**)&dW2h, g_W2h);

    convert_kernel<<<16384, 256>>>(W1, W2);                       // launch 1
    router_kernel<<<N_TOK / 128, 128>>>(x, wg, bg);               // launch 2 (fused scan)
    scatter_gather_kernel<<<N_TOK / 128, 128>>>(x);               // launch 3

    dim3 g1(MLP / BN, N_TOK / BM, NEXP);                          // launch 4
    gemm_fp16<1><<<g1, 256, SMEM_TOT>>>(dW1h, b1, dX, (void*)dH, DMODEL, MLP);
    dim3 g2(DMODEL / BN, N_TOK / BM, NEXP);                       // launch 5
    gemm_fp16<2><<<g2, 256, SMEM_TOT>>>(dW2h, b2, dH, (void*)out, MLP, DMODEL);
}

// round 16
// speedup vs baseline: 1.0008x; 1.0008x over previous
#include <cuda_runtime.h>
#include <cuda_fp16.h>
#include <math.h>
#include <stdint.h>

#define N_TOK 4096
#define DMODEL 1024
#define MLP 4096
#define NEXP 8

// ---------------- device scratch ----------------
__device__ float  g_p[N_TOK];
__device__ int    g_route[N_TOK];
__device__ int    g_cnt[NEXP];
__device__ int    g_off[NEXP + 1];
__device__ int    g_fill[NEXP];
__device__ int    g_perm[N_TOK];
__device__ int    g_done;
__device__ __half g_Xh[(size_t)N_TOK * DMODEL];          // gathered inputs, fp16
__device__ __half g_Hh[(size_t)N_TOK * MLP];             // hidden activations, fp16
__device__ __half g_W1h[(size_t)NEXP * DMODEL * MLP];    // 64 MB fp16 weights
__device__ __half g_W2h[(size_t)NEXP * MLP * DMODEL];    // 64 MB fp16 weights

// ---------------- weight conversion (fp32 -> fp16) ----------------
#define W_F4 8388608   // float4 count per weight tensor (8*1024*4096/4)
__global__ void convert_kernel(const float* __restrict__ W1, const float* __restrict__ W2) {
    int gid = blockIdx.x * 256 + threadIdx.x;          // 16384 blocks * 256
    const int NT = 16384 * 256;
#pragma unroll
    for (int q = 0; q < 4; q++) {
        int idx = gid + q * NT;
        const float4* src; __half* dst;
        if (idx < W_F4) { src = reinterpret_cast<const float4*>(W1) + idx; dst = g_W1h + (size_t)idx * 4; }
        else            { src = reinterpret_cast<const float4*>(W2) + (idx - W_F4); dst = g_W2h + (size_t)(idx - W_F4) * 4; }
        float4 v = *src;
        __half2 h0 = __floats2half2_rn(v.x, v.y);
        __half2 h1 = __floats2half2_rn(v.z, v.w);
        uint2 o;
        o.x = *reinterpret_cast<uint32_t*>(&h0);
        o.y = *reinterpret_cast<uint32_t*>(&h1);
        *reinterpret_cast<uint2*>(dst) = o;
    }
}

// ---------------- router (+ fused scan in last block) ----------------
__global__ void router_kernel(const float* __restrict__ x,
                              const float* __restrict__ wg,
                              const float* __restrict__ bg) {
    __shared__ float sw[DMODEL * NEXP];
    int tid = threadIdx.x;
    for (int i = tid; i < DMODEL * NEXP; i += 128) sw[i] = wg[i];
    __syncthreads();
    int t = blockIdx.x * 128 + tid;
    const float* xr = x + (size_t)t * DMODEL;
    float acc[NEXP];
#pragma unroll
    for (int e = 0; e < NEXP; e++) acc[e] = bg[e];
    for (int d = 0; d < DMODEL; d++) {
        float xv = xr[d];
#pragma unroll
        for (int e = 0; e < NEXP; e++) acc[e] += xv * sw[d * NEXP + e];
    }
    float mx = acc[0]; int mi = 0;
#pragma unroll
    for (int e = 1; e < NEXP; e++) if (acc[e] > mx) { mx = acc[e]; mi = e; }
    float s = 0.f;
#pragma unroll
    for (int e = 0; e < NEXP; e++) s += expf(acc[e] - mx);
    g_p[t] = 1.0f / s;
    g_route[t] = mi;
    atomicAdd(&g_cnt[mi], 1);

    __threadfence();
    __syncthreads();
    if (tid == 0) {
        int v = atomicAdd(&g_done, 1);
        if (v == (int)gridDim.x - 1) {
            __threadfence();
            int acc2 = 0;
            for (int e = 0; e < NEXP; e++) {
                int c = g_cnt[e];
                g_off[e] = acc2; g_fill[e] = acc2; acc2 += c;
                g_cnt[e] = 0;                 // reset for next launch
            }
            g_off[NEXP] = acc2;
            g_done = 0;                       // reset for next launch
            __threadfence();
        }
    }
}

// ---------------- scatter + gather fused ----------------
// 32 blocks x 128 threads; each thread owns one token: get dest row, then the
// block cooperatively copies its 128 rows (fp32 -> fp16).
__global__ void scatter_gather_kernel(const float* __restrict__ x) {
    __shared__ int s_pos[128];
    int tid = threadIdx.x;
    int t = blockIdx.x * 128 + tid;
    int e = g_route[t];
    int pos = atomicAdd(&g_fill[e], 1);
    s_pos[tid] = pos;
    g_perm[pos] = t;
    __syncthreads();
    for (int r = 0; r < 128; r++) {
        int tok = blockIdx.x * 128 + r;
        int pp = s_pos[r];
        const float4* src = reinterpret_cast<const float4*>(x + (size_t)tok * DMODEL);
#pragma unroll
        for (int j = 0; j < 2; j++) {
            int idx = tid + j * 128;          // 0..255 float4
            float4 v = src[idx];
            __half2 h0 = __floats2half2_rn(v.x, v.y);
            __half2 h1 = __floats2half2_rn(v.z, v.w);
            uint2 o;
            o.x = *reinterpret_cast<uint32_t*>(&h0);
            o.y = *reinterpret_cast<uint32_t*>(&h1);
            *reinterpret_cast<uint2*>(g_Xh + (size_t)pp * DMODEL + idx * 4) = o;
        }
    }
}

// ---------------- fp16 tensor-core grouped GEMM, cp.async 3-stage ----------------
#define BM 128
#define BN 128
#define BK 64
#define NST 3
#define AST_B 144                    // A row stride bytes (72 halves)
#define BST_B 272                    // B row stride bytes (136 halves)
#define ASTG (BM * AST_B)            // 18432 B / stage
#define BSTG (BK * BST_B)            // 17408 B / stage
#define STG (ASTG + BSTG)            // 35840
#define SMEM_TOT (NST * STG)         // 107520

__device__ __forceinline__ void cp16(uint32_t dst, const void* src, uint32_t sz) {
    asm volatile("cp.async.cg.shared.global [%0], [%1], 16, %2;"
                 :: "r"(dst), "l"(src), "r"(sz));
}
__device__ __forceinline__ void cp_commit() { asm volatile("cp.async.commit_group;"); }
__device__ __forceinline__ void cp_wait1()  { asm volatile("cp.async.wait_group 1;"); }

__device__ __forceinline__ void ldsm_x4(uint32_t& r0, uint32_t& r1, uint32_t& r2, uint32_t& r3,
                                        uint32_t addr) {
    asm volatile("ldmatrix.sync.aligned.m8n8.x4.shared.b16 {%0,%1,%2,%3}, [%4];"
                 : "=r"(r0), "=r"(r1), "=r"(r2), "=r"(r3) : "r"(addr));
}
__device__ __forceinline__ void ldsm_x4_t(uint32_t& r0, uint32_t& r1, uint32_t& r2, uint32_t& r3,
                                          uint32_t addr) {
    asm volatile("ldmatrix.sync.aligned.m8n8.x4.trans.shared.b16 {%0,%1,%2,%3}, [%4];"
                 : "=r"(r0), "=r"(r1), "=r"(r2), "=r"(r3) : "r"(addr));
}
__device__ __forceinline__ void mma_fp16(float c[4], const uint32_t a[4], const uint32_t b[2]) {
    asm volatile(
        "mma.sync.aligned.m16n8k16.row.col.f32.f16.f16.f32 "
        "{%0,%1,%2,%3}, {%4,%5,%6,%7}, {%8,%9}, {%0,%1,%2,%3};\n"
        : "+f"(c[0]), "+f"(c[1]), "+f"(c[2]), "+f"(c[3])
        : "r"(a[0]), "r"(a[1]), "r"(a[2]), "r"(a[3]), "r"(b[0]), "r"(b[1]));
}

// issue one stage's cp.async fills (A 1024 chunks, B 1024 chunks of 16B)
__device__ __forceinline__ void issue_stage(uint32_t sA, uint32_t sB,
                                            const __half* A, const __half* Bg,
                                            int K, int N, int k0, int mrows, int tid) {
#pragma unroll
    for (int i = 0; i < 4; i++) {
        int c = tid + 256 * i;
        int row = c >> 3;                         // 0..127
        int col8 = (c & 7) * 8;                   // halves
        const __half* src = A + (size_t)(row < mrows ? row : 0) * K + k0 + col8;
        cp16(sA + row * AST_B + (c & 7) * 16, src, row < mrows ? 16u : 0u);
    }
#pragma unroll
    for (int i = 0; i < 4; i++) {
        int c = tid + 256 * i;
        int row = c >> 4;                         // 0..63
        int col16 = (c & 15);                     // 16B chunk
        const __half* src = Bg + (size_t)(k0 + row) * N + col16 * 8;
        cp16(sB + row * BST_B + col16 * 16, src, 16u);
    }
    cp_commit();
}

// EPI = 1: Cdst = g_Hh (half), relu(A@B + bias)
// EPI = 2: Cdst = out (float), (A@B + bias) * p[tok], row-scattered
template <int EPI>
__global__ __launch_bounds__(256)
void gemm_fp16(const __half* __restrict__ Bmat, const float* __restrict__ bias_all,
               const __half* __restrict__ Asrc, void* __restrict__ Cdst,
               int K, int N) {
    int e = blockIdx.z;
    int row_end = g_off[e + 1];
    int row0 = g_off[e] + blockIdx.y * BM;
    if (row0 >= row_end) return;
    int mrows = min(row_end - row0, BM);
    int n0 = blockIdx.x * BN;

    const __half* A = Asrc + (size_t)row0 * K;
    const __half* Bg = Bmat + (size_t)e * K * N + n0;

    extern __shared__ char smem[];
    uint32_t s32 = (uint32_t)__cvta_generic_to_shared(smem);

    int tid = threadIdx.x;
    int warp = tid >> 5, lane = tid & 31;
    int wm = (warp >> 2) * 64;
    int wn = (warp & 3) * 32;
    int g = lane >> 2, tig = lane & 3;

    float c[4][4][4];
#pragma unroll
    for (int i = 0; i < 4; i++)
#pragma unroll
        for (int j = 0; j < 4; j++)
#pragma unroll
            for (int r = 0; r < 4; r++) c[i][j][r] = 0.f;

    uint32_t a_lane = (uint32_t)((wm + (lane & 15)) * AST_B + (lane >> 4) * 16);
    uint32_t b_lane = (uint32_t)(((lane & 7) + ((lane >> 3) & 1) * 8) * BST_B
                                 + (wn + (lane >> 4) * 8) * 2);

    const int nch = K / BK;

    // prologue: fill stages 0,1
#pragma unroll
    for (int s = 0; s < NST - 1; s++)
        issue_stage(s32 + s * STG, s32 + s * STG + ASTG, A, Bg, K, N, s * BK, mrows, tid);

    for (int ch = 0; ch < nch; ch++) {
        cp_wait1();
        __syncthreads();

        // refill stage ch+2 (its old contents were consumed in iteration ch-1)
        if (ch + NST - 1 < nch) {
            int s = (ch + NST - 1) % NST;
            issue_stage(s32 + s * STG, s32 + s * STG + ASTG, A, Bg, K, N,
                        (ch + NST - 1) * BK, mrows, tid);
        } else {
            cp_commit();   // keep group count in lockstep for wait_group 1
        }

        // compute on stage ch%NST
        uint32_t abase = s32 + (ch % NST) * STG + a_lane;
        uint32_t bbase = s32 + (ch % NST) * STG + ASTG + b_lane;
#pragma unroll
        for (int ks = 0; ks < 4; ks++) {
            int kk = ks * 16;
            uint32_t af[4][4], bf[4][2];
#pragma unroll
            for (int i = 0; i < 4; i++)
                ldsm_x4(af[i][0], af[i][1], af[i][2], af[i][3],
                        abase + (uint32_t)(i * 16 * AST_B + kk * 2));
#pragma unroll
            for (int jp = 0; jp < 2; jp++)
                ldsm_x4_t(bf[2 * jp][0], bf[2 * jp][1], bf[2 * jp + 1][0], bf[2 * jp + 1][1],
                          bbase + (uint32_t)(kk * BST_B + jp * 32));
#pragma unroll
            for (int i = 0; i < 4; i++)
#pragma unroll
                for (int j = 0; j < 4; j++) mma_fp16(c[i][j], af[i], bf[j]);
        }
        __syncthreads();
    }

    // ---------------- epilogue ----------------
    const float* bias = bias_all + (size_t)e * N + n0;
#pragma unroll
    for (int i = 0; i < 4; i++) {
#pragma unroll
        for (int r2 = 0; r2 < 2; r2++) {
            int mr = wm + i * 16 + g + r2 * 8;
            if (mr >= mrows) continue;
            int grow = row0 + mr;
            if (EPI == 1) {
                __half* orow = (__half*)Cdst + (size_t)grow * N + n0;
#pragma unroll
                for (int j = 0; j < 4; j++) {
                    int nc = wn + j * 8 + 2 * tig;
                    float v0 = c[i][j][2 * r2]     + bias[nc];
                    float v1 = c[i][j][2 * r2 + 1] + bias[nc + 1];
                    v0 = v0 > 0.f ? v0 : 0.f;
                    v1 = v1 > 0.f ? v1 : 0.f;
                    __half2 h = __floats2half2_rn(v0, v1);
                    *reinterpret_cast<__half2*>(orow + nc) = h;
                }
            } else {
                int tok = g_perm[grow];
                float p = g_p[tok];
                float* orow = (float*)Cdst + (size_t)tok * N + n0;
#pragma unroll
                for (int j = 0; j < 4; j++) {
                    int nc = wn + j * 8 + 2 * tig;
                    float2 o;
                    o.x = (c[i][j][2 * r2]     + bias[nc])     * p;
                    o.y = (c[i][j][2 * r2 + 1] + bias[nc + 1]) * p;
                    *reinterpret_cast<float2*>(orow + nc) = o;
                }
            }
        }
    }
}

// ---------------- launch ----------------
extern "C" void kernel_launch(void* const* d_in, const int* in_sizes, int n_in,
                              void* d_out, int out_size) {
    const float* x   = (const float*)d_in[0];
    const float* wg  = (const float*)d_in[1];
    const float* bg  = (const float*)d_in[2];
    const float* W1  = (const float*)d_in[3];
    const float* b1  = (const float*)d_in[4];
    const float* W2  = (const float*)d_in[5];
    const float* b2  = (const float*)d_in[6];
    float* out = (float*)d_out;

    cudaFuncSetAttribute(gemm_fp16<1>, cudaFuncAttributeMaxDynamicSharedMemorySize, SMEM_TOT);
    cudaFuncSetAttribute(gemm_fp16<2>, cudaFuncAttributeMaxDynamicSharedMemorySize, SMEM_TOT);

    __half *dX = nullptr, *dH = nullptr, *dW1h = nullptr, *dW2h = nullptr;
    cudaGetSymbolAddress((void**)&dX, g_Xh);
    cudaGetSymbolAddress((void**)&dH, g_Hh);
    cudaGetSymbolAddress((void**)&dW1h, g_W1h);
    cudaGetSymbolAddress((void**)&dW2h, g_W2h);

    convert_kernel<<<16384, 256>>>(W1, W2);                       // launch 1
    router_kernel<<<N_TOK / 128, 128>>>(x, wg, bg);               // launch 2 (fused scan)
    scatter_gather_kernel<<<N_TOK / 128, 128>>>(x);               // launch 3

    dim3 g1(MLP / BN, N_TOK / BM, NEXP);                          // launch 4
    gemm_fp16<1><<<g1, 256, SMEM_TOT>>>(dW1h, b1, dX, (void*)dH, DMODEL, MLP);
    dim3 g2(DMODEL / BN, N_TOK / BM, NEXP);                       // launch 5
    gemm_fp16<2><<<g2, 256, SMEM_TOT>>>(dW2h, b2, dH, (void*)out, MLP, DMODEL);
}

// round 17
// speedup vs baseline: 1.0017x; 1.0010x over previous
#include <cuda_runtime.h>
#include <cuda_fp16.h>
#include <math.h>
#include <stdint.h>

#define N_TOK 4096
#define DMODEL 1024
#define MLP 4096
#define NEXP 8

// ---------------- device scratch ----------------
__device__ float  g_p[N_TOK];
__device__ int    g_route[N_TOK];
__device__ int    g_cnt[NEXP];
__device__ int    g_off[NEXP + 1];
__device__ int    g_fill[NEXP];
__device__ int    g_perm[N_TOK];
__device__ int    g_done;
__device__ __half g_Xh[(size_t)N_TOK * DMODEL];          // gathered inputs, fp16
__device__ __half g_Hh[(size_t)N_TOK * MLP];             // hidden activations, fp16
__device__ __half g_W1h[(size_t)NEXP * DMODEL * MLP];    // 64 MB fp16 weights
__device__ __half g_W2h[(size_t)NEXP * MLP * DMODEL];    // 64 MB fp16 weights

// ---------------- weight conversion (fp32 -> fp16) ----------------
#define W_F4 8388608   // float4 count per weight tensor (8*1024*4096/4)
__global__ void convert_kernel(const float* __restrict__ W1, const float* __restrict__ W2) {
    int gid = blockIdx.x * 256 + threadIdx.x;          // 16384 blocks * 256
    const int NT = 16384 * 256;
#pragma unroll
    for (int q = 0; q < 4; q++) {
        int idx = gid + q * NT;
        const float4* src; __half* dst;
        if (idx < W_F4) { src = reinterpret_cast<const float4*>(W1) + idx; dst = g_W1h + (size_t)idx * 4; }
        else            { src = reinterpret_cast<const float4*>(W2) + (idx - W_F4); dst = g_W2h + (size_t)(idx - W_F4) * 4; }
        float4 v = *src;
        __half2 h0 = __floats2half2_rn(v.x, v.y);
        __half2 h1 = __floats2half2_rn(v.z, v.w);
        uint2 o;
        o.x = *reinterpret_cast<uint32_t*>(&h0);
        o.y = *reinterpret_cast<uint32_t*>(&h1);
        *reinterpret_cast<uint2*>(dst) = o;
    }
}

// ---------------- router (+ fused scan in last block) ----------------
__global__ void router_kernel(const float* __restrict__ x,
                              const float* __restrict__ wg,
                              const float* __restrict__ bg) {
    __shared__ float sw[DMODEL * NEXP];
    int tid = threadIdx.x;
    for (int i = tid; i < DMODEL * NEXP; i += 128) sw[i] = wg[i];
    __syncthreads();
    int t = blockIdx.x * 128 + tid;
    const float* xr = x + (size_t)t * DMODEL;
    float acc[NEXP];
#pragma unroll
    for (int e = 0; e < NEXP; e++) acc[e] = bg[e];
    for (int d = 0; d < DMODEL; d++) {
        float xv = xr[d];
#pragma unroll
        for (int e = 0; e < NEXP; e++) acc[e] += xv * sw[d * NEXP + e];
    }
    float mx = acc[0]; int mi = 0;
#pragma unroll
    for (int e = 1; e < NEXP; e++) if (acc[e] > mx) { mx = acc[e]; mi = e; }
    float s = 0.f;
#pragma unroll
    for (int e = 0; e < NEXP; e++) s += expf(acc[e] - mx);
    g_p[t] = 1.0f / s;
    g_route[t] = mi;
    atomicAdd(&g_cnt[mi], 1);

    __threadfence();
    __syncthreads();
    if (tid == 0) {
        int v = atomicAdd(&g_done, 1);
        if (v == (int)gridDim.x - 1) {
            __threadfence();
            int acc2 = 0;
            for (int e = 0; e < NEXP; e++) {
                int c = g_cnt[e];
                g_off[e] = acc2; g_fill[e] = acc2; acc2 += c;
                g_cnt[e] = 0;                 // reset for next launch
            }
            g_off[NEXP] = acc2;
            g_done = 0;                       // reset for next launch
            __threadfence();
        }
    }
}

// ---------------- scatter + gather fused ----------------
// 32 blocks x 128 threads; each thread owns one token: get dest row, then the
// block cooperatively copies its 128 rows (fp32 -> fp16).
__global__ void scatter_gather_kernel(const float* __restrict__ x) {
    __shared__ int s_pos[128];
    int tid = threadIdx.x;
    int t = blockIdx.x * 128 + tid;
    int e = g_route[t];
    int pos = atomicAdd(&g_fill[e], 1);
    s_pos[tid] = pos;
    g_perm[pos] = t;
    __syncthreads();
    for (int r = 0; r < 128; r++) {
        int tok = blockIdx.x * 128 + r;
        int pp = s_pos[r];
        const float4* src = reinterpret_cast<const float4*>(x + (size_t)tok * DMODEL);
#pragma unroll
        for (int j = 0; j < 2; j++) {
            int idx = tid + j * 128;          // 0..255 float4
            float4 v = src[idx];
            __half2 h0 = __floats2half2_rn(v.x, v.y);
            __half2 h1 = __floats2half2_rn(v.z, v.w);
            uint2 o;
            o.x = *reinterpret_cast<uint32_t*>(&h0);
            o.y = *reinterpret_cast<uint32_t*>(&h1);
            *reinterpret_cast<uint2*>(g_Xh + (size_t)pp * DMODEL + idx * 4) = o;
        }
    }
}

// ---------------- fp16 tensor-core grouped GEMM, cp.async 3-stage ----------------
#define BM 128
#define BN 128
#define BK 64
#define NST 3
#define AST_B 144                    // A row stride bytes (72 halves)
#define BST_B 272                    // B row stride bytes (136 halves)
#define ASTG (BM * AST_B)            // 18432 B / stage
#define BSTG (BK * BST_B)            // 17408 B / stage
#define STG (ASTG + BSTG)            // 35840
#define SMEM_TOT (NST * STG)         // 107520

__device__ __forceinline__ void cp16(uint32_t dst, const void* src, uint32_t sz) {
    asm volatile("cp.async.cg.shared.global [%0], [%1], 16, %2;"
                 :: "r"(dst), "l"(src), "r"(sz));
}
__device__ __forceinline__ void cp_commit() { asm volatile("cp.async.commit_group;"); }
__device__ __forceinline__ void cp_wait1()  { asm volatile("cp.async.wait_group 1;"); }

__device__ __forceinline__ void ldsm_x4(uint32_t& r0, uint32_t& r1, uint32_t& r2, uint32_t& r3,
                                        uint32_t addr) {
    asm volatile("ldmatrix.sync.aligned.m8n8.x4.shared.b16 {%0,%1,%2,%3}, [%4];"
                 : "=r"(r0), "=r"(r1), "=r"(r2), "=r"(r3) : "r"(addr));
}
__device__ __forceinline__ void ldsm_x4_t(uint32_t& r0, uint32_t& r1, uint32_t& r2, uint32_t& r3,
                                          uint32_t addr) {
    asm volatile("ldmatrix.sync.aligned.m8n8.x4.trans.shared.b16 {%0,%1,%2,%3}, [%4];"
                 : "=r"(r0), "=r"(r1), "=r"(r2), "=r"(r3) : "r"(addr));
}
__device__ __forceinline__ void mma_fp16(float c[4], const uint32_t a[4], const uint32_t b[2]) {
    asm volatile(
        "mma.sync.aligned.m16n8k16.row.col.f32.f16.f16.f32 "
        "{%0,%1,%2,%3}, {%4,%5,%6,%7}, {%8,%9}, {%0,%1,%2,%3};\n"
        : "+f"(c[0]), "+f"(c[1]), "+f"(c[2]), "+f"(c[3])
        : "r"(a[0]), "r"(a[1]), "r"(a[2]), "r"(a[3]), "r"(b[0]), "r"(b[1]));
}

// issue one stage's cp.async fills (A 1024 chunks, B 1024 chunks of 16B)
__device__ __forceinline__ void issue_stage(uint32_t sA, uint32_t sB,
                                            const __half* A, const __half* Bg,
                                            int K, int N, int k0, int mrows, int tid) {
#pragma unroll
    for (int i = 0; i < 4; i++) {
        int c = tid + 256 * i;
        int row = c >> 3;                         // 0..127
        int col8 = (c & 7) * 8;                   // halves
        const __half* src = A + (size_t)(row < mrows ? row : 0) * K + k0 + col8;
        cp16(sA + row * AST_B + (c & 7) * 16, src, row < mrows ? 16u : 0u);
    }
#pragma unroll
    for (int i = 0; i < 4; i++) {
        int c = tid + 256 * i;
        int row = c >> 4;                         // 0..63
        int col16 = (c & 15);                     // 16B chunk
        const __half* src = Bg + (size_t)(k0 + row) * N + col16 * 8;
        cp16(sB + row * BST_B + col16 * 16, src, 16u);
    }
    cp_commit();
}

// EPI = 1: Cdst = g_Hh (half), relu(A@B + bias)
// EPI = 2: Cdst = out (float), (A@B + bias) * p[tok], row-scattered
template <int EPI>
__global__ __launch_bounds__(256)
void gemm_fp16(const __half* __restrict__ Bmat, const float* __restrict__ bias_all,
               const __half* __restrict__ Asrc, void* __restrict__ Cdst,
               int K, int N) {
    int e = blockIdx.z;
    int row_end = g_off[e + 1];
    int row0 = g_off[e] + blockIdx.y * BM;
    if (row0 >= row_end) return;
    int mrows = min(row_end - row0, BM);
    int n0 = blockIdx.x * BN;

    const __half* A = Asrc + (size_t)row0 * K;
    const __half* Bg = Bmat + (size_t)e * K * N + n0;

    extern __shared__ char smem[];
    uint32_t s32 = (uint32_t)__cvta_generic_to_shared(smem);

    int tid = threadIdx.x;
    int warp = tid >> 5, lane = tid & 31;
    int wm = (warp >> 2) * 64;
    int wn = (warp & 3) * 32;
    int g = lane >> 2, tig = lane & 3;

    float c[4][4][4];
#pragma unroll
    for (int i = 0; i < 4; i++)
#pragma unroll
        for (int j = 0; j < 4; j++)
#pragma unroll
            for (int r = 0; r < 4; r++) c[i][j][r] = 0.f;

    uint32_t a_lane = (uint32_t)((wm + (lane & 15)) * AST_B + (lane >> 4) * 16);
    uint32_t b_lane = (uint32_t)(((lane & 7) + ((lane >> 3) & 1) * 8) * BST_B
                                 + (wn + (lane >> 4) * 8) * 2);

    const int nch = K / BK;

    // prologue: fill stages 0,1
#pragma unroll
    for (int s = 0; s < NST - 1; s++)
        issue_stage(s32 + s * STG, s32 + s * STG + ASTG, A, Bg, K, N, s * BK, mrows, tid);

    for (int ch = 0; ch < nch; ch++) {
        cp_wait1();
        __syncthreads();

        // refill stage ch+2 (its old contents were consumed in iteration ch-1)
        if (ch + NST - 1 < nch) {
            int s = (ch + NST - 1) % NST;
            issue_stage(s32 + s * STG, s32 + s * STG + ASTG, A, Bg, K, N,
                        (ch + NST - 1) * BK, mrows, tid);
        } else {
            cp_commit();   // keep group count in lockstep for wait_group 1
        }

        // compute on stage ch%NST
        uint32_t abase = s32 + (ch % NST) * STG + a_lane;
        uint32_t bbase = s32 + (ch % NST) * STG + ASTG + b_lane;
#pragma unroll
        for (int ks = 0; ks < 4; ks++) {
            int kk = ks * 16;
            uint32_t af[4][4], bf[4][2];
#pragma unroll
            for (int i = 0; i < 4; i++)
                ldsm_x4(af[i][0], af[i][1], af[i][2], af[i][3],
                        abase + (uint32_t)(i * 16 * AST_B + kk * 2));
#pragma unroll
            for (int jp = 0; jp < 2; jp++)
                ldsm_x4_t(bf[2 * jp][0], bf[2 * jp][1], bf[2 * jp + 1][0], bf[2 * jp + 1][1],
                          bbase + (uint32_t)(kk * BST_B + jp * 32));
#pragma unroll
            for (int i = 0; i < 4; i++)
#pragma unroll
                for (int j = 0; j < 4; j++) mma_fp16(c[i][j], af[i], bf[j]);
        }
        __syncthreads();
    }

    // ---------------- epilogue ----------------
    const float* bias = bias_all + (size_t)e * N + n0;
#pragma unroll
    for (int i = 0; i < 4; i++) {
#pragma unroll
        for (int r2 = 0; r2 < 2; r2++) {
            int mr = wm + i * 16 + g + r2 * 8;
            if (mr >= mrows) continue;
            int grow = row0 + mr;
            if (EPI == 1) {
                __half* orow = (__half*)Cdst + (size_t)grow * N + n0;
#pragma unroll
                for (int j = 0; j < 4; j++) {
                    int nc = wn + j * 8 + 2 * tig;
                    float v0 = c[i][j][2 * r2]     + bias[nc];
                    float v1 = c[i][j][2 * r2 + 1] + bias[nc + 1];
                    v0 = v0 > 0.f ? v0 : 0.f;
                    v1 = v1 > 0.f ? v1 : 0.f;
                    __half2 h = __floats2half2_rn(v0, v1);
                    *reinterpret_cast<__half2*>(orow + nc) = h;
                }
            } else {
                int tok = g_perm[grow];
                float p = g_p[tok];
                float* orow = (float*)Cdst + (size_t)tok * N + n0;
#pragma unroll
                for (int j = 0; j < 4; j++) {
                    int nc = wn + j * 8 + 2 * tig;
                    float2 o;
                    o.x = (c[i][j][2 * r2]     + bias[nc])     * p;
                    o.y = (c[i][j][2 * r2 + 1] + bias[nc + 1]) * p;
                    *reinterpret_cast<float2*>(orow + nc) = o;
                }
            }
        }
    }
}

// ---------------- launch ----------------
extern "C" void kernel_launch(void* const* d_in, const int* in_sizes, int n_in,
                              void* d_out, int out_size) {
    const float* x   = (const float*)d_in[0];
    const float* wg  = (const float*)d_in[1];
    const float* bg  = (const float*)d_in[2];
    const float* W1  = (const float*)d_in[3];
    const float* b1  = (const float*)d_in[4];
    const float* W2  = (const float*)d_in[5];
    const float* b2  = (const float*)d_in[6];
    float* out = (float*)d_out;

    cudaFuncSetAttribute(gemm_fp16<1>, cudaFuncAttributeMaxDynamicSharedMemorySize, SMEM_TOT);
    cudaFuncSetAttribute(gemm_fp16<2>, cudaFuncAttributeMaxDynamicSharedMemorySize, SMEM_TOT);

    __half *dX = nullptr, *dH = nullptr, *dW1h = nullptr, *dW2h = nullptr;
    cudaGetSymbolAddress((void**)&dX, g_Xh);
    cudaGetSymbolAddress((void**)&dH, g_Hh);
    cudaGetSymbolAddress((void**)&dW1h, g_W1h);
    cudaGetSymbolAddress((void**)&dW2h, g_W2h);

    convert_kernel<<<16384, 256>>>(W1, W2);                       // launch 1
    router_kernel<<<N_TOK / 128, 128>>>(x, wg, bg);               // launch 2 (fused scan)
    scatter_gather_kernel<<<N_TOK / 128, 128>>>(x);               // launch 3

    dim3 g1(MLP / BN, N_TOK / BM, NEXP);                          // launch 4
    gemm_fp16<1><<<g1, 256, SMEM_TOT>>>(dW1h, b1, dX, (void*)dH, DMODEL, MLP);
    dim3 g2(DMODEL / BN, N_TOK / BM, NEXP);                       // launch 5
    gemm_fp16<2><<<g2, 256, SMEM_TOT>>>(dW2h, b2, dH, (void*)out, MLP, DMODEL);
}